// round 9
// baseline (speedup 1.0000x reference)
#include <cuda_runtime.h>
#include <cuda_fp16.h>

// Problem shape (fixed for this problem instance)
#define BB 4
#define NN 32768
#define CC 128
#define DD 32
#define VV (DD * DD * DD)       // 32768

#define NT_TILES (BB * 1024)    // 4096 transpose tiles (32 voxels x 128 ch)
#define NS_UNITS ((BB * NN) / 8)// 16384 sample units (8 points each)
#define GRID_P   592            // 148 SMs x 4 CTAs -- co-resident guaranteed

// Scratch: channel-last transposed features in fp16, (B, V, C). 33.5 MB ->
// L2-resident. fp16 rounding <= 2^-11 rel (measured 2.1e-4 vs 1e-3 limit).
__device__ __half g_trans[(size_t)BB * VV * CC];

// Work-queue state (reset by init_k every launch -- graph replays reuse it).
__device__ unsigned g_tctr;       // transpose tile counter
__device__ unsigned g_sctr;       // sample unit counter
__device__ unsigned g_done[BB];   // completed transpose tiles per batch

__global__ void init_k() {
    g_tctr = 0u;
    g_sctr = 0u;
    #pragma unroll
    for (int b = 0; b < BB; b++) g_done[b] = 0u;
}

// ---------------------------------------------------------------------------
// Persistent fused kernel: software-pipelined transpose -> sample.
// Phase 1 (transpose): batch-major tile queue. Per tile: 4 x LDG.128
// (evict-first), [128][33] smem stage, 4 x 8B fp16 stores; then
// threadfence + g_done[b]++.
// Phase 2 (sample): batch-major unit queue. Unit = 8 points, one warp per
// point, spin-wait until its batch's 1024 tiles are done, then 8 predicated
// 8B gathers per thread (L2-hit) + 8 coalesced STG.128 evict-first stores.
// Overlap: while early CTAs sample batch b (DRAM writes), late CTAs still
// transpose batches b+1.. (DRAM reads) -> read/write streams share HBM.
// ---------------------------------------------------------------------------
__global__ __launch_bounds__(256, 4)
void fused_k(const float* __restrict__ in,
             const float* __restrict__ pt,
             float* __restrict__ out) {
    __shared__ float tile[128][33];
    __shared__ unsigned s_work;
    const int tid = threadIdx.x;

    // ---------------- Phase 1: transpose ----------------
    for (;;) {
        if (tid == 0) s_work = atomicAdd(&g_tctr, 1u);
        __syncthreads();
        const unsigned t = s_work;
        if (t >= NT_TILES) break;

        const int b  = (int)(t >> 10);          // batch-major
        const int v0 = (int)(t & 1023u) << 5;   // 32-voxel slab

        // Read phase: 4 x (channel row c_i, voxel float4 v4), MLP=4
        {
            const int v4 = tid & 7;
            float4 f[4];
            #pragma unroll
            for (int j = 0; j < 4; j++) {
                const int c_i = 32 * j + (tid >> 3);
                f[j] = __ldcs((const float4*)
                    (in + ((size_t)b * CC + c_i) * VV + (v0 + 4 * v4)));
            }
            #pragma unroll
            for (int j = 0; j < 4; j++) {
                const int c_i = 32 * j + (tid >> 3);
                tile[c_i][4 * v4 + 0] = f[j].x;
                tile[c_i][4 * v4 + 1] = f[j].y;
                tile[c_i][4 * v4 + 2] = f[j].z;
                tile[c_i][4 * v4 + 3] = f[j].w;
            }
        }
        __syncthreads();
        // Write phase: 4 x (voxel row v_i, 4-channel group c4) -> 8B pair
        {
            const int v_i = tid >> 3;
            #pragma unroll
            for (int j = 0; j < 4; j++) {
                const int c4 = (tid & 7) + 8 * j;
                const __half2 h0 = __floats2half2_rn(tile[4 * c4 + 0][v_i],
                                                     tile[4 * c4 + 1][v_i]);
                const __half2 h1 = __floats2half2_rn(tile[4 * c4 + 2][v_i],
                                                     tile[4 * c4 + 3][v_i]);
                uint2 packed;
                *reinterpret_cast<__half2*>(&packed.x) = h0;
                *reinterpret_cast<__half2*>(&packed.y) = h1;
                *(uint2*)(g_trans +
                    ((size_t)b * VV + (v0 + v_i)) * CC + 4 * c4) = packed;
            }
        }
        __threadfence();      // each thread releases its scratch stores
        __syncthreads();      // all fences done; also guards tile & s_work
        if (tid == 0) atomicAdd(&g_done[b], 1u);
    }

    // ---------------- Phase 2: sample ----------------
    const float scale = (DD - 1) * 0.5f;        // 15.5
    for (;;) {
        if (tid == 0) s_work = atomicAdd(&g_sctr, 1u);
        __syncthreads();
        const unsigned w = s_work;
        if (w >= NS_UNITS) break;

        const int b = (int)(w >> 12);           // 4096 units per batch
        if (tid == 0) {                         // wait: batch fully transposed
            unsigned d;
            do { d = *(volatile unsigned*)&g_done[b]; } while (d < 1024u);
        }
        __syncthreads();
        __threadfence();                        // acquire before gathers

        const int bn   = (int)(w * 8u) + (tid >> 5);  // point id
        const int lane = tid & 31;

        const float px = (__ldg(&pt[(size_t)3 * bn + 0]) + 1.0f) * scale;
        const float py = (__ldg(&pt[(size_t)3 * bn + 1]) + 1.0f) * scale;
        const float pz = (__ldg(&pt[(size_t)3 * bn + 2]) + 1.0f) * scale;
        const int lx = (int)floorf(px);
        const int ly = (int)floorf(py);
        const int lz = (int)floorf(pz);

        const __half* base = g_trans + (size_t)b * VV * CC;

        uint2 v[8];
        #pragma unroll
        for (int k = 0; k < 8; k++) {
            const int ix = lx + ((k >> 2) & 1);
            const int iy = ly + ((k >> 1) & 1);
            const int iz = lz + (k & 1);
            const bool valid =
                ((unsigned)ix < DD) & ((unsigned)iy < DD) & ((unsigned)iz < DD);
            v[k] = make_uint2(0u, 0u);
            if (valid) {
                const int flat = (ix * DD + iy) * DD + iz;
                v[k] = __ldg((const uint2*)(base + (size_t)flat * CC) + lane);
            }
        }

        float4* dst = (float4*)(out + (size_t)bn * 8 * CC) + lane;
        #pragma unroll
        for (int k = 0; k < 8; k++) {
            const float2 lo =
                __half22float2(*reinterpret_cast<const __half2*>(&v[k].x));
            const float2 hi =
                __half22float2(*reinterpret_cast<const __half2*>(&v[k].y));
            __stcs(dst + (size_t)k * 32, make_float4(lo.x, lo.y, hi.x, hi.y));
        }
        __syncthreads();                        // guard s_work for next iter
    }
}

// ---------------------------------------------------------------------------
// Launch
// ---------------------------------------------------------------------------
extern "C" void kernel_launch(void* const* d_in, const int* in_sizes, int n_in,
                              void* d_out, int out_size) {
    const float* ptcloud = (const float*)d_in[0];  // (B, N, 3)
    const float* feats   = (const float*)d_in[1];  // (B, C, D, D, D)
    float* out           = (float*)d_out;          // (B, N, 8, C)

    init_k<<<1, 1>>>();
    fused_k<<<GRID_P, 256>>>(feats, ptcloud, out);
}

// round 10
// speedup vs baseline: 1.2113x; 1.2113x over previous
#include <cuda_runtime.h>
#include <cuda_fp16.h>

// Problem shape (fixed for this problem instance)
#define BB 4
#define NN 32768
#define CC 128
#define DD 32
#define VV (DD * DD * DD)   // 32768

// Scratch: channel-last transposed features in fp16, (B, V, C). 33.5 MB ->
// L2-resident (verified: sample_k DRAM traffic == output stream alone).
// Gather is a pure copy, so fp16 rounding (<=2^-11 rel) is the only error
// source; measured 2.1e-4 vs the 1e-3 threshold (~5x margin).
//
// Converged design notes (from R1-R9 measurements):
//  - Mandatory DRAM traffic: 536 MB out-writes + 64 MB feats-reads = 600 MB
//    -> ~96-97 us floor at the ~6.2 TB/s achieved ceiling. This kernel runs
//    within ~2% of that floor.
//  - HBM bandwidth is shared read/write: phase overlap (R9 persistent fusion)
//    cannot beat the serial two-kernel schedule and only adds overhead.
//  - MLP=8 per thread is sufficient to reach the ceiling; MLP=16 (R3) and
//    bigger transpose tiles (R7) are neutral-to-negative.
__device__ __half g_trans[(size_t)BB * VV * CC];

// ---------------------------------------------------------------------------
// Kernel 1: transpose + downconvert (B, C, V) fp32 -> (B, V, C) fp16.
// One block: 128-channel x 32-voxel slab via [128][33] fp32 smem tile
// (16.9 KB -> 13 CTAs/SM). Read: 4 independent LDG.128 per thread
// (evict-first: zero reuse). Write: 4 x STG.64 of half2 pairs, coalesced
// along channels, default policy so scratch lines land (and stay) in L2.
// ---------------------------------------------------------------------------
__global__ __launch_bounds__(256)
void transpose_k(const float* __restrict__ in) {
    __shared__ float tile[128][33];
    const int b   = blockIdx.y;
    const int v0  = blockIdx.x * 32;
    const int tid = threadIdx.x;

    // Read phase: 4 x (channel row c_i, voxel float4 v4)
    {
        const int v4 = tid & 7;                 // 0..7 -> voxel float4
        float4 f[4];
        #pragma unroll
        for (int j = 0; j < 4; j++) {
            const int c_i = 32 * j + (tid >> 3);  // 0..127
            f[j] = __ldcs((const float4*)
                (in + ((size_t)b * CC + c_i) * VV + (v0 + 4 * v4)));
        }
        #pragma unroll
        for (int j = 0; j < 4; j++) {
            const int c_i = 32 * j + (tid >> 3);
            tile[c_i][4 * v4 + 0] = f[j].x;
            tile[c_i][4 * v4 + 1] = f[j].y;
            tile[c_i][4 * v4 + 2] = f[j].z;
            tile[c_i][4 * v4 + 3] = f[j].w;
        }
    }
    __syncthreads();
    // Write phase: 4 x (voxel row v_i, 4-channel group c4) -> 8B half2 pair
    {
        const int v_i = tid >> 3;               // 0..31
        #pragma unroll
        for (int j = 0; j < 4; j++) {
            const int c4 = (tid & 7) + 8 * j;   // 0..31 -> channel group of 4
            const __half2 h0 = __floats2half2_rn(tile[4 * c4 + 0][v_i],
                                                 tile[4 * c4 + 1][v_i]);
            const __half2 h1 = __floats2half2_rn(tile[4 * c4 + 2][v_i],
                                                 tile[4 * c4 + 3][v_i]);
            uint2 packed;
            *reinterpret_cast<__half2*>(&packed.x) = h0;
            *reinterpret_cast<__half2*>(&packed.y) = h1;
            *(uint2*)(g_trans + ((size_t)b * VV + (v0 + v_i)) * CC + 4 * c4)
                = packed;
        }
    }
}

// ---------------------------------------------------------------------------
// Kernel 2: per-point trilinear-corner gather, one WARP per point.
// Lane = one 4-channel chunk. Per corner: one predicated 8B fp16 load
// (warp reads 256B contiguous, L2-hit on the resident scratch) -> MLP=8 per
// thread. Upconvert to fp32 and store 8 coalesced STG.128 (4KB/warp, evict-
// first so the write stream doesn't displace the scratch in L2).
// Pinned at the HBM write ceiling (~6.25 TB/s DRAM; LTS read+write combined
// ~9.8 TB/s, near the chip LTS cap).
// ---------------------------------------------------------------------------
__global__ __launch_bounds__(256)
void sample_k(const float* __restrict__ pt, float* __restrict__ out) {
    const int bn   = blockIdx.x * 8 + (threadIdx.x >> 5);  // point id
    const int b    = bn >> 15;                             // N = 32768
    const int lane = threadIdx.x & 31;

    const float scale = (DD - 1) * 0.5f;  // 15.5
    const float px = (__ldg(&pt[(size_t)3 * bn + 0]) + 1.0f) * scale;
    const float py = (__ldg(&pt[(size_t)3 * bn + 1]) + 1.0f) * scale;
    const float pz = (__ldg(&pt[(size_t)3 * bn + 2]) + 1.0f) * scale;

    const int lx = (int)floorf(px);
    const int ly = (int)floorf(py);
    const int lz = (int)floorf(pz);

    const __half* base = g_trans + (size_t)b * VV * CC;

    uint2 v[8];
    #pragma unroll
    for (int k = 0; k < 8; k++) {
        const int ix = lx + ((k >> 2) & 1);
        const int iy = ly + ((k >> 1) & 1);
        const int iz = lz + (k & 1);
        const bool valid =
            ((unsigned)ix < DD) & ((unsigned)iy < DD) & ((unsigned)iz < DD);
        v[k] = make_uint2(0u, 0u);
        if (valid) {
            const int flat = (ix * DD + iy) * DD + iz;
            v[k] = __ldg((const uint2*)(base + (size_t)flat * CC) + lane);
        }
    }

    float4* dst = (float4*)(out + (size_t)bn * 8 * CC) + lane;
    #pragma unroll
    for (int k = 0; k < 8; k++) {
        const float2 lo =
            __half22float2(*reinterpret_cast<const __half2*>(&v[k].x));
        const float2 hi =
            __half22float2(*reinterpret_cast<const __half2*>(&v[k].y));
        __stcs(dst + (size_t)k * 32, make_float4(lo.x, lo.y, hi.x, hi.y));
    }
}

// ---------------------------------------------------------------------------
// Launch
// ---------------------------------------------------------------------------
extern "C" void kernel_launch(void* const* d_in, const int* in_sizes, int n_in,
                              void* d_out, int out_size) {
    const float* ptcloud = (const float*)d_in[0];  // (B, N, 3)
    const float* feats   = (const float*)d_in[1];  // (B, C, D, D, D)
    float* out           = (float*)d_out;          // (B, N, 8, C)

    dim3 tgrid(VV / 32, BB);            // (1024, 4)
    transpose_k<<<tgrid, 256>>>(feats);

    sample_k<<<(BB * NN) / 8, 256>>>(ptcloud, out);
}